// round 10
// baseline (speedup 1.0000x reference)
#include <cuda_runtime.h>

// SCSA fused v9 = v8 (152x1024 persistent occ-1, fine-grained units, .cs,
// unroll-8) with barrier-minimal control:
//  - double-buffered work-steal slot: no loop-top barriers, atomic latency
//    hidden behind the unit's own first barrier; fast warps flow into the
//    next unit's streaming while slow warps finish the previous one.
//  - warp-local MLP: warp c owns channel c end-to-end (conv1 row in regs ->
//    GN -> hswish -> s_y row -> conv_hw row -> pass B). 2 CTA barriers per
//    spatial unit instead of 6.

#define NCTAS   152
#define THREADS 1024
#define NUNITS  1280

__device__ unsigned int g_counter;
__global__ void reset_counter_k() { g_counter = 0u; }

__device__ __forceinline__ float sigmoidf_(float z) {
    return 1.f / (1.f + __expf(-z));
}
__device__ __forceinline__ float sigapx_(float z) {
    float t;
    asm("tanh.approx.f32 %0, %1;" : "=f"(t) : "f"(z * 0.5f));
    return fmaf(0.5f, t, 0.5f);
}
__device__ __forceinline__ float hswishf_(float z) {
    return z * __saturatef((z + 3.f) * (1.f / 6.f));
}
__device__ __forceinline__ int shuffle_out_ch(int p) {
    return (p < 256) ? (2 * p) : (2 * (p - 256) + 1);
}

__global__ __launch_bounds__(THREADS, 1) void scsa_persistent(
    const float* __restrict__ x,
    const float* __restrict__ cweight, const float* __restrict__ cbias,
    const float* __restrict__ conv1_w, const float* __restrict__ conv1_b,
    const float* __restrict__ gn_g,    const float* __restrict__ gn_b,
    const float* __restrict__ convh_w, const float* __restrict__ convh_b,
    const float* __restrict__ convw_w, const float* __restrict__ convw_b,
    float* __restrict__ out)
{
    __shared__ float s_red[4096];   // row c: xh[0..63] | xw[64..127]; aliased as a (a_h|a_w)
    __shared__ float s_y[4096];
    __shared__ float s_w1[1024], s_wh[1024], s_ww[1024];
    __shared__ float s_b1[32], s_bh[32], s_bw[32], s_gg[32], s_gb[32], s_xs[32];
    __shared__ float s_part[32];    // channel-quarter partials [ch8*4 + rowblk]
    __shared__ float s_gate[8];
    __shared__ unsigned s_u[2];
    float* s_a = s_red;

    const int tid  = threadIdx.x;
    const int wid  = tid >> 5;       // warp id; spatial: warp = channel c
    const int lane = tid & 31;
    const int half = lane >> 4;
    const int q    = lane & 15;
    const int c    = wid;

    // stage weights once (published by prologue barrier)
    s_w1[tid] = conv1_w[tid];
    s_wh[tid] = convh_w[tid];
    s_ww[tid] = convw_w[tid];
    if (tid < 32) {
        s_b1[tid] = conv1_b[tid]; s_bh[tid] = convh_b[tid]; s_bw[tid] = convw_b[tid];
        s_gg[tid] = gn_g[tid];    s_gb[tid] = gn_b[tid];
    }
    if (tid == 0) s_u[0] = atomicAdd(&g_counter, 1u);
    __syncthreads();
    unsigned u = s_u[0];
    int par = 1;

    while (u < NUNITS) {
        // steal next unit into the other slot; published by this unit's B1.
        if (tid == 0) s_u[par] = atomicAdd(&g_counter, 1u);

        // ---------------- unit decode ----------------
        const bool is_spatial = (u < 512) && !(u & 1u);
        int bb, qd = 0;
        if (is_spatial) {
            bb = (int)(u >> 1);
        } else {
            const int cq = (u < 512) ? (int)(u >> 1) : (int)(u - 256);
            bb = cq >> 2; qd = cq & 3;
        }
        const int n = bb >> 3, g = bb & 7;

        if (!is_spatial) {
            // ========== channel-quarter: x0 channels g*64 + qd*8 + [0,8) ==========
            const int ch8 = wid & 7;
            const int rb  = wid >> 3;
            const int cglob = g * 64 + qd * 8 + ch8;
            const float4* xq4 = (const float4*)(x + ((size_t)(n * 512 + cglob)) * 4096)
                              + rb * 256;
            float s = 0.f;
            {
                float4 v[8];
                #pragma unroll
                for (int j = 0; j < 8; j++) v[j] = xq4[j * 32 + lane];
                #pragma unroll
                for (int j = 0; j < 8; j++)
                    s += (v[j].x + v[j].y) + (v[j].z + v[j].w);
            }
            #pragma unroll
            for (int o = 16; o; o >>= 1) s += __shfl_xor_sync(0xffffffffu, s, o);
            if (lane == 0) s_part[ch8 * 4 + rb] = s;
            __syncthreads();                  // B1: publishes s_part and s_u[par]
            const unsigned unext = s_u[par];
            if (tid < 8) {
                const float tot = s_part[tid * 4] + s_part[tid * 4 + 1]
                                + s_part[tid * 4 + 2] + s_part[tid * 4 + 3];
                const int cg = qd * 8 + tid;
                s_gate[tid] = sigmoidf_(cweight[cg] * (tot * (1.f / 4096.f)) + cbias[cg]);
            }
            __syncthreads();                  // B2: publishes s_gate
            const float gate = s_gate[ch8];
            float4* od = (float4*)(out + ((size_t)(n * 512 + shuffle_out_ch(cglob))) * 4096)
                       + rb * 256;
            {
                float4 v[8];
                #pragma unroll
                for (int j = 0; j < 8; j++) v[j] = __ldcs(&xq4[j * 32 + lane]);
                #pragma unroll
                for (int j = 0; j < 8; j++) {
                    v[j].x *= gate; v[j].y *= gate; v[j].z *= gate; v[j].w *= gate;
                    __stcs(&od[j * 32 + lane], v[j]);
                }
            }
            u = unext; par ^= 1;
            continue;
        }

        // ================= spatial unit: x1 of block bb =================
        const float4* xc4 = (const float4*)(x + ((size_t)(n * 512 + g * 64 + 32 + c)) * 4096);

        // ---- Pass A: row/col/total means. 8 loads in flight per warp. ----
        float cs0 = 0.f, cs1 = 0.f, cs2 = 0.f, cs3 = 0.f, xs = 0.f;
        #pragma unroll
        for (int tt = 0; tt < 32; tt += 8) {
            float4 v[8];
            #pragma unroll
            for (int j = 0; j < 8; j++) v[j] = xc4[(tt + j) * 32 + lane];
            float r[8];
            #pragma unroll
            for (int j = 0; j < 8; j++) {
                cs0 += v[j].x; cs1 += v[j].y; cs2 += v[j].z; cs3 += v[j].w;
                r[j] = (v[j].x + v[j].y) + (v[j].z + v[j].w);
                xs += r[j];
            }
            #pragma unroll
            for (int o = 8; o; o >>= 1) {
                #pragma unroll
                for (int j = 0; j < 8; j++)
                    r[j] += __shfl_xor_sync(0xffffffffu, r[j], o);
            }
            if (q == 0) {
                #pragma unroll
                for (int j = 0; j < 8; j++)
                    s_red[c * 128 + 2 * (tt + j) + half] = r[j] * (1.f / 64.f);
            }
        }
        cs0 += __shfl_xor_sync(0xffffffffu, cs0, 16);
        cs1 += __shfl_xor_sync(0xffffffffu, cs1, 16);
        cs2 += __shfl_xor_sync(0xffffffffu, cs2, 16);
        cs3 += __shfl_xor_sync(0xffffffffu, cs3, 16);
        #pragma unroll
        for (int o = 16; o; o >>= 1) xs += __shfl_xor_sync(0xffffffffu, xs, o);
        if (half == 0) {
            ((float4*)(s_red + c * 128 + 64))[q] = make_float4(
                cs0 * (1.f / 64.f), cs1 * (1.f / 64.f),
                cs2 * (1.f / 64.f), cs3 * (1.f / 64.f));
        }
        if (lane == 0) s_xs[c] = xs * (1.f / 4096.f);
        __syncthreads();                      // B1: publishes s_red, s_xs, s_u[par]
        const unsigned unext = s_u[par];

        // ---- conv1 row c, y in registers (lane owns p = lane + 32j) ----
        float y0, y1, y2, y3;
        {
            const float b = s_b1[c];
            y0 = b; y1 = b; y2 = b; y3 = b;
            const float* w1r = s_w1 + c * 32;
            #pragma unroll 8
            for (int i = 0; i < 32; i++) {
                const float w = w1r[i];
                const float* rr = s_red + i * 128 + lane;
                y0 = fmaf(w, rr[0],  y0);
                y1 = fmaf(w, rr[32], y1);
                y2 = fmaf(w, rr[64], y2);
                y3 = fmaf(w, rr[96], y3);
            }
        }
        // ---- GroupNorm(128) + h-swish on registers (warp-local) ----
        {
            float s1 = (y0 + y1) + (y2 + y3);
            float s2 = fmaf(y0, y0, fmaf(y1, y1, fmaf(y2, y2, y3 * y3)));
            #pragma unroll
            for (int o = 16; o; o >>= 1) {
                s1 += __shfl_xor_sync(0xffffffffu, s1, o);
                s2 += __shfl_xor_sync(0xffffffffu, s2, o);
            }
            const float mu  = s1 * (1.f / 128.f);
            const float var = s2 * (1.f / 128.f) - mu * mu;
            const float gm  = s_gg[c] * rsqrtf(var + 1e-5f);
            const float gc  = fmaf(-mu, gm, s_gb[c]);
            y0 = hswishf_(fmaf(y0, gm, gc));
            y1 = hswishf_(fmaf(y1, gm, gc));
            y2 = hswishf_(fmaf(y2, gm, gc));
            y3 = hswishf_(fmaf(y3, gm, gc));
            float* yw = s_y + c * 128;
            yw[lane] = y0; yw[lane + 32] = y1; yw[lane + 64] = y2; yw[lane + 96] = y3;
        }
        __syncthreads();                      // B2: publishes s_y (all rows)

        // ---- conv_h/conv_w row c (reads all s_y, writes only s_a row c) ----
        {
            const float* whr = s_wh + c * 32;
            const float* wwr = s_ww + c * 32;
            float a0 = s_bh[c], a1 = s_bh[c], a2 = s_bw[c], a3 = s_bw[c];
            #pragma unroll 8
            for (int i = 0; i < 32; i++) {
                const float wh = whr[i], ww = wwr[i];
                const float* yr = s_y + i * 128 + lane;
                a0 = fmaf(wh, yr[0],  a0);   // p = lane      (a_h)
                a1 = fmaf(wh, yr[32], a1);   // p = lane + 32 (a_h)
                a2 = fmaf(ww, yr[64], a2);   // p = lane + 64 (a_w)
                a3 = fmaf(ww, yr[96], a3);   // p = lane + 96 (a_w)
            }
            float* ar = s_a + c * 128;
            ar[lane] = a0; ar[lane + 32] = a1; ar[lane + 64] = a2; ar[lane + 96] = a3;
        }
        __syncwarp();                         // row c visible within warp c

        // ---- Pass B: gate + channel-shuffled store (L2-hit re-read) ----
        const float xsv = s_xs[c];
        float4 aw = ((const float4*)(s_a + c * 128 + 64))[q];
        const float g0 = aw.x * xsv, g1 = aw.y * xsv, g2 = aw.z * xsv, g3 = aw.w * xsv;
        float4* od = (float4*)(out + ((size_t)(n * 512 + shuffle_out_ch(g * 64 + 32 + c))) * 4096);
        #pragma unroll
        for (int tt = 0; tt < 32; tt += 8) {
            float4 v[8];
            #pragma unroll
            for (int j = 0; j < 8; j++) v[j] = __ldcs(&xc4[(tt + j) * 32 + lane]);
            #pragma unroll
            for (int j = 0; j < 8; j++) {
                const float ah = s_a[c * 128 + 2 * (tt + j) + half];
                v[j].x *= sigapx_(ah * g0);
                v[j].y *= sigapx_(ah * g1);
                v[j].z *= sigapx_(ah * g2);
                v[j].w *= sigapx_(ah * g3);
                __stcs(&od[(tt + j) * 32 + lane], v[j]);
            }
        }
        u = unext; par ^= 1;
    }
}

extern "C" void kernel_launch(void* const* d_in, const int* in_sizes, int n_in,
                              void* d_out, int out_size) {
    const float* x       = (const float*)d_in[0];
    const float* cweight = (const float*)d_in[1];
    const float* cbias   = (const float*)d_in[2];
    const float* conv1_w = (const float*)d_in[3];
    const float* conv1_b = (const float*)d_in[4];
    const float* gn_g    = (const float*)d_in[5];
    const float* gn_b    = (const float*)d_in[6];
    const float* convh_w = (const float*)d_in[7];
    const float* convh_b = (const float*)d_in[8];
    const float* convw_w = (const float*)d_in[9];
    const float* convw_b = (const float*)d_in[10];
    float* out = (float*)d_out;

    reset_counter_k<<<1, 1>>>();
    scsa_persistent<<<NCTAS, THREADS>>>(
        x, cweight, cbias, conv1_w, conv1_b, gn_g, gn_b,
        convh_w, convh_b, convw_w, convw_b, out);
}

// round 11
// speedup vs baseline: 1.0271x; 1.0271x over previous
#include <cuda_runtime.h>

// SCSA fused v10 = v8 internals (152x1024 persistent occ-1, fine-grained units,
// position-blocked convs, .cs, unroll-8) + v9's good part only:
//  - double-buffered work-steal slot s_u[2]: loop-top barriers removed; the
//    atomic is issued at unit start and published by the unit's first internal
//    barrier. Fast warps flow directly into the next unit's streaming.
//  - channel-quarter: ONE barrier (s_part parity-double-buffered; every thread
//    computes its gate redundantly from the 4 partials; s_gate eliminated).
// Cross-unit smem safety: pass A writes / pass B reads are warp-row-local;
// conv phases sit strictly between the unit's internal barriers.

#define NCTAS   152
#define THREADS 1024
#define NUNITS  1280

__device__ unsigned int g_counter;
__global__ void reset_counter_k() { g_counter = 0u; }

__device__ __forceinline__ float sigmoidf_(float z) {
    return 1.f / (1.f + __expf(-z));
}
__device__ __forceinline__ float sigapx_(float z) {
    float t;
    asm("tanh.approx.f32 %0, %1;" : "=f"(t) : "f"(z * 0.5f));
    return fmaf(0.5f, t, 0.5f);
}
__device__ __forceinline__ float hswishf_(float z) {
    return z * __saturatef((z + 3.f) * (1.f / 6.f));
}
__device__ __forceinline__ int shuffle_out_ch(int p) {
    return (p < 256) ? (2 * p) : (2 * (p - 256) + 1);
}

__global__ __launch_bounds__(THREADS, 1) void scsa_persistent(
    const float* __restrict__ x,
    const float* __restrict__ cweight, const float* __restrict__ cbias,
    const float* __restrict__ conv1_w, const float* __restrict__ conv1_b,
    const float* __restrict__ gn_g,    const float* __restrict__ gn_b,
    const float* __restrict__ convh_w, const float* __restrict__ convh_b,
    const float* __restrict__ convw_w, const float* __restrict__ convw_b,
    float* __restrict__ out)
{
    __shared__ float s_red[4096];   // row c: xh[0..63] | xw[64..127]; aliased as a_h|a_w
    __shared__ float s_y[4096];
    __shared__ float s_w1[1024], s_wh[1024], s_ww[1024];
    __shared__ float s_b1[32], s_bh[32], s_bw[32], s_gg[32], s_gb[32], s_xs[32];
    __shared__ float s_part[2][32]; // channel-quarter partials, parity-buffered
    __shared__ unsigned s_u[2];
    float* s_a = s_red;

    const int tid  = threadIdx.x;
    const int wid  = tid >> 5;       // warp id; spatial: warp = channel c
    const int lane = tid & 31;
    const int half = lane >> 4;
    const int q    = lane & 15;
    const int t7   = tid >> 7;       // 0..7 conv output-block id
    const int pp   = tid & 127;      // conv position id
    const int c    = wid;

    // stage weights once (published by prologue barrier)
    s_w1[tid] = conv1_w[tid];
    s_wh[tid] = convh_w[tid];
    s_ww[tid] = convw_w[tid];
    if (tid < 32) {
        s_b1[tid] = conv1_b[tid]; s_bh[tid] = convh_b[tid]; s_bw[tid] = convw_b[tid];
        s_gg[tid] = gn_g[tid];    s_gb[tid] = gn_b[tid];
    }
    if (tid == 0) s_u[0] = atomicAdd(&g_counter, 1u);
    __syncthreads();
    unsigned u = s_u[0];
    int par = 1;

    while (u < NUNITS) {
        // steal next unit into the other slot; published by this unit's B1.
        if (tid == 0) s_u[par] = atomicAdd(&g_counter, 1u);

        // ---------------- unit decode ----------------
        const bool is_spatial = (u < 512) && !(u & 1u);
        int bb, qd = 0;
        if (is_spatial) {
            bb = (int)(u >> 1);
        } else {
            const int cq = (u < 512) ? (int)(u >> 1) : (int)(u - 256);
            bb = cq >> 2; qd = cq & 3;
        }
        const int n = bb >> 3, g = bb & 7;

        if (!is_spatial) {
            // ========== channel-quarter: x0 channels g*64 + qd*8 + [0,8) ==========
            const int ch8 = wid & 7;
            const int rb  = wid >> 3;
            const int cglob = g * 64 + qd * 8 + ch8;
            const float4* xq4 = (const float4*)(x + ((size_t)(n * 512 + cglob)) * 4096)
                              + rb * 256;
            float s = 0.f;
            {
                float4 v[8];
                #pragma unroll
                for (int j = 0; j < 8; j++) v[j] = xq4[j * 32 + lane];
                #pragma unroll
                for (int j = 0; j < 8; j++)
                    s += (v[j].x + v[j].y) + (v[j].z + v[j].w);
            }
            #pragma unroll
            for (int o = 16; o; o >>= 1) s += __shfl_xor_sync(0xffffffffu, s, o);
            if (lane == 0) s_part[par][ch8 * 4 + rb] = s;
            __syncthreads();                  // B1: publishes s_part[par] and s_u[par]
            const unsigned unext = s_u[par];
            // per-thread redundant gate (no second barrier)
            const float tot = s_part[par][ch8 * 4] + s_part[par][ch8 * 4 + 1]
                            + s_part[par][ch8 * 4 + 2] + s_part[par][ch8 * 4 + 3];
            const int cg = qd * 8 + ch8;      // channel within the 32-wide x0 half
            const float gate = sigmoidf_(cweight[cg] * (tot * (1.f / 4096.f)) + cbias[cg]);

            float4* od = (float4*)(out + ((size_t)(n * 512 + shuffle_out_ch(cglob))) * 4096)
                       + rb * 256;
            {
                float4 v[8];
                #pragma unroll
                for (int j = 0; j < 8; j++) v[j] = __ldcs(&xq4[j * 32 + lane]);
                #pragma unroll
                for (int j = 0; j < 8; j++) {
                    v[j].x *= gate; v[j].y *= gate; v[j].z *= gate; v[j].w *= gate;
                    __stcs(&od[j * 32 + lane], v[j]);
                }
            }
            u = unext; par ^= 1;
            continue;
        }

        // ================= spatial unit: x1 of block bb =================
        const float4* xc4 = (const float4*)(x + ((size_t)(n * 512 + g * 64 + 32 + c)) * 4096);

        // ---- Pass A: row/col/total means. 8 loads in flight per warp. ----
        // (writes only s_red row c + s_xs[c] -> warp-local across units)
        float cs0 = 0.f, cs1 = 0.f, cs2 = 0.f, cs3 = 0.f, xs = 0.f;
        #pragma unroll
        for (int tt = 0; tt < 32; tt += 8) {
            float4 v[8];
            #pragma unroll
            for (int j = 0; j < 8; j++) v[j] = xc4[(tt + j) * 32 + lane];
            float r[8];
            #pragma unroll
            for (int j = 0; j < 8; j++) {
                cs0 += v[j].x; cs1 += v[j].y; cs2 += v[j].z; cs3 += v[j].w;
                r[j] = (v[j].x + v[j].y) + (v[j].z + v[j].w);
                xs += r[j];
            }
            #pragma unroll
            for (int o = 8; o; o >>= 1) {
                #pragma unroll
                for (int j = 0; j < 8; j++)
                    r[j] += __shfl_xor_sync(0xffffffffu, r[j], o);
            }
            if (q == 0) {
                #pragma unroll
                for (int j = 0; j < 8; j++)
                    s_red[c * 128 + 2 * (tt + j) + half] = r[j] * (1.f / 64.f);
            }
        }
        cs0 += __shfl_xor_sync(0xffffffffu, cs0, 16);
        cs1 += __shfl_xor_sync(0xffffffffu, cs1, 16);
        cs2 += __shfl_xor_sync(0xffffffffu, cs2, 16);
        cs3 += __shfl_xor_sync(0xffffffffu, cs3, 16);
        #pragma unroll
        for (int o = 16; o; o >>= 1) xs += __shfl_xor_sync(0xffffffffu, xs, o);
        if (half == 0) {
            ((float4*)(s_red + c * 128 + 64))[q] = make_float4(
                cs0 * (1.f / 64.f), cs1 * (1.f / 64.f),
                cs2 * (1.f / 64.f), cs3 * (1.f / 64.f));
        }
        if (lane == 0) s_xs[c] = xs * (1.f / 4096.f);
        __syncthreads();                      // B1: publishes s_red, s_xs, s_u[par]
        const unsigned unext = s_u[par];

        // ---- conv1, register-blocked: outputs o = t7, 8+t7, 16+t7, 24+t7 ----
        {
            float acc0 = s_b1[t7], acc1 = s_b1[8 + t7], acc2 = s_b1[16 + t7], acc3 = s_b1[24 + t7];
            const int wb = t7 * 32;
            #pragma unroll 8
            for (int i = 0; i < 32; i++) {
                const float xv = s_red[i * 128 + pp];
                acc0 = fmaf(s_w1[wb + i],       xv, acc0);
                acc1 = fmaf(s_w1[wb + 256 + i], xv, acc1);
                acc2 = fmaf(s_w1[wb + 512 + i], xv, acc2);
                acc3 = fmaf(s_w1[wb + 768 + i], xv, acc3);
            }
            s_y[t7 * 128 + pp]        = acc0;
            s_y[(8 + t7) * 128 + pp]  = acc1;
            s_y[(16 + t7) * 128 + pp] = acc2;
            s_y[(24 + t7) * 128 + pp] = acc3;
        }
        __syncthreads();                      // B2

        // ---- GroupNorm(128) + h-swish, warp per channel ----
        {
            float* yr = s_y + c * 128;
            float v0 = yr[lane], v1 = yr[lane + 32], v2 = yr[lane + 64], v3 = yr[lane + 96];
            float s1 = (v0 + v1) + (v2 + v3);
            float s2 = fmaf(v0, v0, fmaf(v1, v1, fmaf(v2, v2, v3 * v3)));
            #pragma unroll
            for (int o = 16; o; o >>= 1) {
                s1 += __shfl_xor_sync(0xffffffffu, s1, o);
                s2 += __shfl_xor_sync(0xffffffffu, s2, o);
            }
            const float mu  = s1 * (1.f / 128.f);
            const float var = s2 * (1.f / 128.f) - mu * mu;
            const float gm  = s_gg[c] * rsqrtf(var + 1e-5f);
            const float gc  = fmaf(-mu, gm, s_gb[c]);
            yr[lane]      = hswishf_(fmaf(v0, gm, gc));
            yr[lane + 32] = hswishf_(fmaf(v1, gm, gc));
            yr[lane + 64] = hswishf_(fmaf(v2, gm, gc));
            yr[lane + 96] = hswishf_(fmaf(v3, gm, gc));
        }
        __syncthreads();                      // B3

        // ---- conv_h/conv_w, register-blocked -> s_a (alias s_red) ----
        {
            const float* w  = (pp < 64) ? s_wh : s_ww;
            const float* bs = (pp < 64) ? s_bh : s_bw;
            float acc0 = bs[t7], acc1 = bs[8 + t7], acc2 = bs[16 + t7], acc3 = bs[24 + t7];
            const int wb = t7 * 32;
            #pragma unroll 8
            for (int i = 0; i < 32; i++) {
                const float yv = s_y[i * 128 + pp];
                acc0 = fmaf(w[wb + i],       yv, acc0);
                acc1 = fmaf(w[wb + 256 + i], yv, acc1);
                acc2 = fmaf(w[wb + 512 + i], yv, acc2);
                acc3 = fmaf(w[wb + 768 + i], yv, acc3);
            }
            s_a[t7 * 128 + pp]        = acc0;
            s_a[(8 + t7) * 128 + pp]  = acc1;
            s_a[(16 + t7) * 128 + pp] = acc2;
            s_a[(24 + t7) * 128 + pp] = acc3;
        }
        __syncthreads();                      // B4

        // ---- Pass B: gate + channel-shuffled store (L2-hit re-read) ----
        // (reads only s_a row c -> warp-local across units)
        const float xsv = s_xs[c];
        float4 aw = ((const float4*)(s_a + c * 128 + 64))[q];
        const float g0 = aw.x * xsv, g1 = aw.y * xsv, g2 = aw.z * xsv, g3 = aw.w * xsv;
        float4* od = (float4*)(out + ((size_t)(n * 512 + shuffle_out_ch(g * 64 + 32 + c))) * 4096);
        #pragma unroll
        for (int tt = 0; tt < 32; tt += 8) {
            float4 v[8];
            #pragma unroll
            for (int j = 0; j < 8; j++) v[j] = __ldcs(&xc4[(tt + j) * 32 + lane]);
            #pragma unroll
            for (int j = 0; j < 8; j++) {
                const float ah = s_a[c * 128 + 2 * (tt + j) + half];
                v[j].x *= sigapx_(ah * g0);
                v[j].y *= sigapx_(ah * g1);
                v[j].z *= sigapx_(ah * g2);
                v[j].w *= sigapx_(ah * g3);
                __stcs(&od[(tt + j) * 32 + lane], v[j]);
            }
        }
        u = unext; par ^= 1;
    }
}

extern "C" void kernel_launch(void* const* d_in, const int* in_sizes, int n_in,
                              void* d_out, int out_size) {
    const float* x       = (const float*)d_in[0];
    const float* cweight = (const float*)d_in[1];
    const float* cbias   = (const float*)d_in[2];
    const float* conv1_w = (const float*)d_in[3];
    const float* conv1_b = (const float*)d_in[4];
    const float* gn_g    = (const float*)d_in[5];
    const float* gn_b    = (const float*)d_in[6];
    const float* convh_w = (const float*)d_in[7];
    const float* convh_b = (const float*)d_in[8];
    const float* convw_w = (const float*)d_in[9];
    const float* convw_b = (const float*)d_in[10];
    float* out = (float*)d_out;

    reset_counter_k<<<1, 1>>>();
    scsa_persistent<<<NCTAS, THREADS>>>(
        x, cweight, cbias, conv1_w, conv1_b, gn_g, gn_b,
        convh_w, convh_b, convw_w, convw_b, out);
}